// round 3
// baseline (speedup 1.0000x reference)
#include <cuda_runtime.h>
#include <cstdint>

// ---------------------------------------------------------------------------
// out[i] = sum_{e: w_rows[e]==i} Param_W[w_params[e]] * x[w_cols[e]]
//          + Param_b[b_params[i]]
//
// Round-2 strategy: x (1MB) lives in DISTRIBUTED SHARED MEMORY across an
// 8-CTA cluster (128KB slice per CTA). Gathers become ld.shared::cluster
// instead of L2 sector fetches, removing ~40% of LTS work (the R1 binding
// resource at 89.9%). Index streams + RED atomics remain on the L2 path.
// ---------------------------------------------------------------------------

#define CLUSTER_SZ   8
#define LOG_SLICE    15
#define SLICE        32768            // floats per CTA slice (128 KB)
#define XCAP         (CLUSTER_SZ * SLICE)   // 262144
#define BLOCK_T      1024
#define NUM_CLUSTERS 16               // 128 CTAs — guaranteed single wave

__global__ void bias_init_kernel(const float* __restrict__ Param_b,
                                 const int*   __restrict__ b_params,
                                 float*       __restrict__ out,
                                 int N)
{
    int i = blockIdx.x * blockDim.x + threadIdx.x;
    if (i < N) {
        out[i] = __ldg(&Param_b[b_params[i]]);
    }
}

__device__ __forceinline__ uint32_t smem_u32(const void* p)
{
    uint32_t a;
    asm("{ .reg .u64 t; cvta.to.shared.u64 t, %1; cvt.u32.u64 %0, t; }"
        : "=r"(a) : "l"(p));
    return a;
}

// Gather one float from the cluster-distributed x cache.
__device__ __forceinline__ float dsmem_gather(uint32_t xs_base, int col)
{
    uint32_t rank  = (uint32_t)col >> LOG_SLICE;
    uint32_t local = xs_base + (((uint32_t)col & (SLICE - 1)) << 2);
    uint32_t remote;
    asm("mapa.shared::cluster.u32 %0, %1, %2;"
        : "=r"(remote) : "r"(local), "r"(rank));
    float v;
    asm volatile("ld.shared::cluster.f32 %0, [%1];" : "=f"(v) : "r"(remote));
    return v;
}

__global__ void __cluster_dims__(CLUSTER_SZ, 1, 1) __launch_bounds__(BLOCK_T, 1)
edge_scatter_dsmem_kernel(const float* __restrict__ x,
                          const float* __restrict__ Param_W,
                          const int4*  __restrict__ rows4,
                          const int4*  __restrict__ cols4,
                          const int4*  __restrict__ params4,
                          float*       __restrict__ out,
                          int E4, int N)
{
    extern __shared__ float xs[];

    uint32_t rank;
    asm("mov.u32 %0, %%cluster_ctarank;" : "=r"(rank));

    // Fill this CTA's 128KB slice of x (coalesced, cheap: 1MB total chip-wide).
    int base = (int)(rank << LOG_SLICE);
    for (int i = threadIdx.x; i < SLICE; i += BLOCK_T) {
        int g = base + i;
        xs[i] = (g < N) ? x[g] : 0.0f;
    }
    // All slices must be resident before any CTA gathers.
    asm volatile("barrier.cluster.arrive.aligned;" ::: "memory");
    asm volatile("barrier.cluster.wait.aligned;"   ::: "memory");

    uint32_t xs_base = smem_u32(xs);

    int stride = gridDim.x * BLOCK_T;
    for (int t = blockIdx.x * BLOCK_T + threadIdx.x; t < E4; t += stride) {
        int4 r = rows4[t];
        int4 c = cols4[t];
        int4 p = params4[t];

        float x0 = dsmem_gather(xs_base, c.x);
        float x1 = dsmem_gather(xs_base, c.y);
        float x2 = dsmem_gather(xs_base, c.z);
        float x3 = dsmem_gather(xs_base, c.w);

        float v0 = __ldg(&Param_W[p.x]) * x0;
        float v1 = __ldg(&Param_W[p.y]) * x1;
        float v2 = __ldg(&Param_W[p.z]) * x2;
        float v3 = __ldg(&Param_W[p.w]) * x3;

        atomicAdd(&out[r.x], v0);
        atomicAdd(&out[r.y], v1);
        atomicAdd(&out[r.z], v2);
        atomicAdd(&out[r.w], v3);
    }

    // No CTA may exit while peers can still read its smem slice.
    asm volatile("barrier.cluster.arrive.aligned;" ::: "memory");
    asm volatile("barrier.cluster.wait.aligned;"   ::: "memory");
}

// Fallback path (unexpected shapes) + scalar tail.
__global__ void edge_scatter_vec4_kernel(const float* __restrict__ x,
                                         const float* __restrict__ Param_W,
                                         const int4*  __restrict__ rows4,
                                         const int4*  __restrict__ cols4,
                                         const int4*  __restrict__ params4,
                                         float*       __restrict__ out,
                                         int E4)
{
    int t = blockIdx.x * blockDim.x + threadIdx.x;
    if (t >= E4) return;
    int4 r = rows4[t];
    int4 c = cols4[t];
    int4 p = params4[t];
    float v0 = __ldg(&Param_W[p.x]) * __ldg(&x[c.x]);
    float v1 = __ldg(&Param_W[p.y]) * __ldg(&x[c.y]);
    float v2 = __ldg(&Param_W[p.z]) * __ldg(&x[c.z]);
    float v3 = __ldg(&Param_W[p.w]) * __ldg(&x[c.w]);
    atomicAdd(&out[r.x], v0);
    atomicAdd(&out[r.y], v1);
    atomicAdd(&out[r.z], v2);
    atomicAdd(&out[r.w], v3);
}

__global__ void edge_scatter_tail_kernel(const float* __restrict__ x,
                                         const float* __restrict__ Param_W,
                                         const int*   __restrict__ rows,
                                         const int*   __restrict__ cols,
                                         const int*   __restrict__ params,
                                         float*       __restrict__ out,
                                         int start, int E)
{
    int e = start + blockIdx.x * blockDim.x + threadIdx.x;
    if (e < E) {
        float v = __ldg(&Param_W[params[e]]) * __ldg(&x[cols[e]]);
        atomicAdd(&out[rows[e]], v);
    }
}

extern "C" void kernel_launch(void* const* d_in, const int* in_sizes, int n_in,
                              void* d_out, int out_size)
{
    const float* x        = (const float*)d_in[0];
    const float* Param_W  = (const float*)d_in[1];
    const float* Param_b  = (const float*)d_in[2];
    const int*   w_rows   = (const int*)  d_in[3];
    const int*   w_cols   = (const int*)  d_in[4];
    const int*   w_params = (const int*)  d_in[5];
    const int*   b_params = (const int*)  d_in[6];
    float*       out      = (float*)d_out;

    const int N = out_size;        // 262144
    const int E = in_sizes[3];     // 16777216

    // 1) out = gathered bias (also clears poison; must precede any atomics).
    {
        int threads = 256;
        int blocks  = (N + threads - 1) / threads;
        bias_init_kernel<<<blocks, threads>>>(Param_b, b_params, out, N);
    }

    int E4 = E / 4;

    if (N <= XCAP) {
        // 2) DSMEM-cached edge scatter.
        static int smem_set = 0;
        if (!smem_set) {
            cudaFuncSetAttribute(edge_scatter_dsmem_kernel,
                                 cudaFuncAttributeMaxDynamicSharedMemorySize,
                                 SLICE * (int)sizeof(float));
            smem_set = 1;
        }
        if (E4 > 0) {
            edge_scatter_dsmem_kernel
                <<<NUM_CLUSTERS * CLUSTER_SZ, BLOCK_T, SLICE * sizeof(float)>>>(
                    x, Param_W,
                    (const int4*)w_rows, (const int4*)w_cols, (const int4*)w_params,
                    out, E4, N);
        }
    } else {
        // Fallback: direct atomic scatter.
        if (E4 > 0) {
            int threads = 256;
            int blocks  = (E4 + threads - 1) / threads;
            edge_scatter_vec4_kernel<<<blocks, threads>>>(
                x, Param_W,
                (const int4*)w_rows, (const int4*)w_cols, (const int4*)w_params,
                out, E4);
        }
    }

    int tail_start = E4 * 4;
    if (E - tail_start > 0) {
        edge_scatter_tail_kernel<<<1, 256>>>(
            x, Param_W, w_rows, w_cols, w_params, out, tail_start, E);
    }
}

// round 4
// speedup vs baseline: 3.2579x; 3.2579x over previous
#include <cuda_runtime.h>
#include <cstdint>

// ---------------------------------------------------------------------------
// out[i] = sum_{e: w_rows[e]==i} Param_W[w_params[e]] * x[w_cols[e]]
//          + Param_b[b_params[i]]
//
// N = 262144, E = 16.7M. Binding resource (R1 ncu): LTS at ~90% with L1 at 83%.
// R3: __ldcs on streaming index loads (protect x's L1 residency),
//     Param_W gathers via smem (offload L1tex), 8 edges/thread.
// ---------------------------------------------------------------------------

#define NPARAMS_MAX 2048   // smem staging capacity for Param_W (actual 1280)

__global__ void bias_init_vec4_kernel(const float* __restrict__ Param_b,
                                      const int4*  __restrict__ b_params4,
                                      float4*      __restrict__ out4,
                                      int N4)
{
    int i = blockIdx.x * blockDim.x + threadIdx.x;
    if (i < N4) {
        int4 b = b_params4[i];
        float4 o;
        o.x = __ldg(&Param_b[b.x]);
        o.y = __ldg(&Param_b[b.y]);
        o.z = __ldg(&Param_b[b.z]);
        o.w = __ldg(&Param_b[b.w]);
        out4[i] = o;
    }
}

__global__ void bias_init_kernel(const float* __restrict__ Param_b,
                                 const int*   __restrict__ b_params,
                                 float*       __restrict__ out,
                                 int start, int N)
{
    int i = start + blockIdx.x * blockDim.x + threadIdx.x;
    if (i < N) out[i] = __ldg(&Param_b[b_params[i]]);
}

// 8 edges per thread. Index streams read with __ldcs (evict-first: read-once
// 201MB must not thrash x's L1 lines). Param_W gathered from smem.
__global__ void __launch_bounds__(256)
edge_scatter_vec8_kernel(const float* __restrict__ x,
                         const float* __restrict__ Param_W,
                         const int4*  __restrict__ rows4,
                         const int4*  __restrict__ cols4,
                         const int4*  __restrict__ params4,
                         float*       __restrict__ out,
                         int E8, int nparams)
{
    __shared__ float sPW[NPARAMS_MAX];
    for (int i = threadIdx.x; i < nparams; i += blockDim.x)
        sPW[i] = Param_W[i];
    __syncthreads();

    int t = blockIdx.x * blockDim.x + threadIdx.x;
    if (t >= E8) return;
    int q = t * 2;

    // Front-batched streaming loads (6 x LDG.128, evict-first).
    int4 r0 = __ldcs(&rows4[q]);
    int4 r1 = __ldcs(&rows4[q + 1]);
    int4 c0 = __ldcs(&cols4[q]);
    int4 c1 = __ldcs(&cols4[q + 1]);
    int4 p0 = __ldcs(&params4[q]);
    int4 p1 = __ldcs(&params4[q + 1]);

    // x gathers: L2-resident (1MB), partially L1-hit.
    float x0 = __ldg(&x[c0.x]);
    float x1 = __ldg(&x[c0.y]);
    float x2 = __ldg(&x[c0.z]);
    float x3 = __ldg(&x[c0.w]);
    float x4 = __ldg(&x[c1.x]);
    float x5 = __ldg(&x[c1.y]);
    float x6 = __ldg(&x[c1.z]);
    float x7 = __ldg(&x[c1.w]);

    float v0 = sPW[p0.x] * x0;
    float v1 = sPW[p0.y] * x1;
    float v2 = sPW[p0.z] * x2;
    float v3 = sPW[p0.w] * x3;
    float v4 = sPW[p1.x] * x4;
    float v5 = sPW[p1.y] * x5;
    float v6 = sPW[p1.z] * x6;
    float v7 = sPW[p1.w] * x7;

    atomicAdd(&out[r0.x], v0);
    atomicAdd(&out[r0.y], v1);
    atomicAdd(&out[r0.z], v2);
    atomicAdd(&out[r0.w], v3);
    atomicAdd(&out[r1.x], v4);
    atomicAdd(&out[r1.y], v5);
    atomicAdd(&out[r1.z], v6);
    atomicAdd(&out[r1.w], v7);
}

__global__ void edge_scatter_tail_kernel(const float* __restrict__ x,
                                         const float* __restrict__ Param_W,
                                         const int*   __restrict__ rows,
                                         const int*   __restrict__ cols,
                                         const int*   __restrict__ params,
                                         float*       __restrict__ out,
                                         int start, int E)
{
    int e = start + blockIdx.x * blockDim.x + threadIdx.x;
    if (e < E) {
        float v = __ldg(&Param_W[params[e]]) * __ldg(&x[cols[e]]);
        atomicAdd(&out[rows[e]], v);
    }
}

extern "C" void kernel_launch(void* const* d_in, const int* in_sizes, int n_in,
                              void* d_out, int out_size)
{
    const float* x        = (const float*)d_in[0];
    const float* Param_W  = (const float*)d_in[1];
    const float* Param_b  = (const float*)d_in[2];
    const int*   w_rows   = (const int*)  d_in[3];
    const int*   w_cols   = (const int*)  d_in[4];
    const int*   w_params = (const int*)  d_in[5];
    const int*   b_params = (const int*)  d_in[6];
    float*       out      = (float*)d_out;

    const int N       = out_size;     // 262144
    const int E       = in_sizes[3];  // 16777216
    const int nparams = in_sizes[1] < NPARAMS_MAX ? in_sizes[1] : NPARAMS_MAX;

    // 1) out = gathered bias (clears poison; must precede atomics).
    {
        int N4 = N / 4;
        if (N4 > 0) {
            int threads = 256;
            int blocks  = (N4 + threads - 1) / threads;
            bias_init_vec4_kernel<<<blocks, threads>>>(
                Param_b, (const int4*)b_params, (float4*)out, N4);
        }
        int rem_start = N4 * 4;
        if (N - rem_start > 0) {
            bias_init_kernel<<<1, 256>>>(Param_b, b_params, out, rem_start, N);
        }
    }

    // 2) Edge scatter, 8 edges/thread.
    {
        int E8 = E / 8;
        if (E8 > 0) {
            int threads = 256;
            int blocks  = (E8 + threads - 1) / threads;
            edge_scatter_vec8_kernel<<<blocks, threads>>>(
                x, Param_W,
                (const int4*)w_rows, (const int4*)w_cols, (const int4*)w_params,
                out, E8, nparams);
        }
        int tail_start = E8 * 8;
        if (E - tail_start > 0) {
            edge_scatter_tail_kernel<<<1, 256>>>(
                x, Param_W, w_rows, w_cols, w_params, out, tail_start, E);
        }
    }
}

// round 5
// speedup vs baseline: 3.4959x; 1.0731x over previous
#include <cuda_runtime.h>
#include <cstdint>

// ---------------------------------------------------------------------------
// out[i] = sum_{e: w_rows[e]==i} Param_W[w_params[e]] * x[w_cols[e]]
//          + Param_b[b_params[i]]
//
// N = 262144, E = 16.7M. Jointly op-rate bound at L1tex + LTS (R1: 83%/90%).
// R4 = R1 structure (4 edges/thread — low MLP_p1, low cross-CTA L1tex-queue
// spread) + __ldcs on the read-once index streams so they don't evict x's
// L1 lines (x is the only reusable data; every extra L1 hit removes an L2 op).
// ---------------------------------------------------------------------------

__global__ void bias_init_vec4_kernel(const float* __restrict__ Param_b,
                                      const int4*  __restrict__ b_params4,
                                      float4*      __restrict__ out4,
                                      int N4)
{
    int i = blockIdx.x * blockDim.x + threadIdx.x;
    if (i < N4) {
        int4 b = b_params4[i];
        float4 o;
        o.x = __ldg(&Param_b[b.x]);
        o.y = __ldg(&Param_b[b.y]);
        o.z = __ldg(&Param_b[b.z]);
        o.w = __ldg(&Param_b[b.w]);
        out4[i] = o;
    }
}

__global__ void bias_init_kernel(const float* __restrict__ Param_b,
                                 const int*   __restrict__ b_params,
                                 float*       __restrict__ out,
                                 int start, int N)
{
    int i = start + blockIdx.x * blockDim.x + threadIdx.x;
    if (i < N) out[i] = __ldg(&Param_b[b_params[i]]);
}

__global__ void __launch_bounds__(256)
edge_scatter_vec4_kernel(const float* __restrict__ x,
                         const float* __restrict__ Param_W,
                         const int4*  __restrict__ rows4,
                         const int4*  __restrict__ cols4,
                         const int4*  __restrict__ params4,
                         float*       __restrict__ out,
                         int E4)
{
    int t = blockIdx.x * blockDim.x + threadIdx.x;
    if (t >= E4) return;

    // Read-once index streams: evict-first so they never displace x in L1.
    int4 r = __ldcs(&rows4[t]);
    int4 c = __ldcs(&cols4[t]);
    int4 p = __ldcs(&params4[t]);

    // x: 1MB, L2-resident, partially L1-resident (the reuse we're protecting).
    // Param_W: 5KB, L1-hot.
    float v0 = __ldg(&Param_W[p.x]) * __ldg(&x[c.x]);
    float v1 = __ldg(&Param_W[p.y]) * __ldg(&x[c.y]);
    float v2 = __ldg(&Param_W[p.z]) * __ldg(&x[c.z]);
    float v3 = __ldg(&Param_W[p.w]) * __ldg(&x[c.w]);

    // No-return atomics -> RED.ADD.F32 at L2 (addresses spread over slices).
    atomicAdd(&out[r.x], v0);
    atomicAdd(&out[r.y], v1);
    atomicAdd(&out[r.z], v2);
    atomicAdd(&out[r.w], v3);
}

__global__ void edge_scatter_tail_kernel(const float* __restrict__ x,
                                         const float* __restrict__ Param_W,
                                         const int*   __restrict__ rows,
                                         const int*   __restrict__ cols,
                                         const int*   __restrict__ params,
                                         float*       __restrict__ out,
                                         int start, int E)
{
    int e = start + blockIdx.x * blockDim.x + threadIdx.x;
    if (e < E) {
        float v = __ldg(&Param_W[params[e]]) * __ldg(&x[cols[e]]);
        atomicAdd(&out[rows[e]], v);
    }
}

extern "C" void kernel_launch(void* const* d_in, const int* in_sizes, int n_in,
                              void* d_out, int out_size)
{
    const float* x        = (const float*)d_in[0];
    const float* Param_W  = (const float*)d_in[1];
    const float* Param_b  = (const float*)d_in[2];
    const int*   w_rows   = (const int*)  d_in[3];
    const int*   w_cols   = (const int*)  d_in[4];
    const int*   w_params = (const int*)  d_in[5];
    const int*   b_params = (const int*)  d_in[6];
    float*       out      = (float*)d_out;

    const int N = out_size;       // 262144
    const int E = in_sizes[3];    // 16777216

    // 1) out = gathered bias (clears poison; must precede atomics).
    {
        int N4 = N / 4;
        if (N4 > 0) {
            int threads = 256;
            int blocks  = (N4 + threads - 1) / threads;
            bias_init_vec4_kernel<<<blocks, threads>>>(
                Param_b, (const int4*)b_params, (float4*)out, N4);
        }
        int rem_start = N4 * 4;
        if (N - rem_start > 0) {
            bias_init_kernel<<<1, 256>>>(Param_b, b_params, out, rem_start, N);
        }
    }

    // 2) Edge scatter, 4 edges/thread (R1-proven shape).
    {
        int E4 = E / 4;
        if (E4 > 0) {
            int threads = 256;
            int blocks  = (E4 + threads - 1) / threads;
            edge_scatter_vec4_kernel<<<blocks, threads>>>(
                x, Param_W,
                (const int4*)w_rows, (const int4*)w_cols, (const int4*)w_params,
                out, E4);
        }
        int tail_start = E4 * 4;
        if (E - tail_start > 0) {
            edge_scatter_tail_kernel<<<1, 256>>>(
                x, Param_W, w_rows, w_cols, w_params, out, tail_start, E);
        }
    }
}